// round 14
// baseline (speedup 1.0000x reference)
#include <cuda_runtime.h>
#include <cuda_fp16.h>
#include <cstdint>

typedef unsigned short ush;
typedef unsigned int uint32;

// ---------------- scratch (device globals; zero-initialized, no allocation) ----------------
__device__ ush g_imgh[2048 * 3 * 7056];   // image fp16 hi, planar [n][c][y*84+x]
__device__ ush g_imgl[2048 * 3 * 7056];
__device__ ush g_a1h[2048 * 400 * 32];    // conv1 out planes [n*400+p][32]
__device__ ush g_a1l[2048 * 400 * 32];
__device__ ush g_a2h[2048 * 81 * 64];     // conv2 out planes
__device__ ush g_a2l[2048 * 81 * 64];
__device__ ush g_a3h[2048 * 49 * 64];     // conv3 out planes [n*49+p][64] (k=p*64+c)
__device__ ush g_a3l[2048 * 49 * 64];
__device__ ush g_hidh[2048 * 8256];       // hidden planes [map 8192 | pos 64]
__device__ ush g_hidl[2048 * 8256];
__device__ float g_h[2048 * 512];         // CNN feature (fp32, feeds wfeat)
__device__ float g_wfeat[2048 * 32];
__device__ float g_part[2 * 2048 * 512];  // split-K partials (FC: 2x2048x512; policy: 8x2048x128)
__device__ float g_z[2048 * 128];
__device__ float g_bcat[128];
// fp16 weight tiles (hi only), packed rows: chunk tile = NT rows x 64 bytes (32 k's).
__device__ uint4 g_w1sw[6 * 128];         // conv1: 6 chunks x 2KB (NT=32)
__device__ uint4 g_w2sw[16 * 256];        // conv2: 16 chunks x 4KB
__device__ uint4 g_w3sw[18 * 256];        // conv3: 18 chunks
__device__ uint4 g_wfcsw[8 * 98 * 256];   // FC: 8 ntiles x 98 chunks
__device__ uint4 g_wposw[2 * 258 * 256];  // policy: 2 ntiles x 258 chunks

// ---------------- helpers ----------------
static __device__ __forceinline__ uint32 s2u(const void* p) {
    uint32 a;
    asm("{ .reg .u64 t; cvta.to.shared.u64 t, %1; cvt.u32.u64 %0, t; }" : "=r"(a) : "l"(p));
    return a;
}
static __device__ __forceinline__ void cpa16(uint32 d, const void* s) {
    asm volatile("cp.async.cg.shared.global [%0], [%1], 16;" :: "r"(d), "l"(s));
}
static __device__ __forceinline__ void cpa8(uint32 d, const void* s) {
    asm volatile("cp.async.ca.shared.global [%0], [%1], 8;" :: "r"(d), "l"(s));
}
static __device__ __forceinline__ void ldsm4(uint32 addr, uint32* r) {
    asm volatile("ldmatrix.sync.aligned.m8n8.x4.shared.b16 {%0,%1,%2,%3}, [%4];"
                 : "=r"(r[0]), "=r"(r[1]), "=r"(r[2]), "=r"(r[3]) : "r"(addr));
}
static __device__ __forceinline__ void ldsm2(uint32 addr, uint32* r) {
    asm volatile("ldmatrix.sync.aligned.m8n8.x2.shared.b16 {%0,%1}, [%2];"
                 : "=r"(r[0]), "=r"(r[1]) : "r"(addr));
}
static __device__ __forceinline__ void mmaF16(float* c, const uint32* a, const uint32* b) {
    asm volatile(
        "mma.sync.aligned.m16n8k16.row.col.f32.f16.f16.f32 "
        "{%0,%1,%2,%3}, {%4,%5,%6,%7}, {%8,%9}, {%0,%1,%2,%3};"
        : "+f"(c[0]), "+f"(c[1]), "+f"(c[2]), "+f"(c[3])
        : "r"(a[0]), "r"(a[1]), "r"(a[2]), "r"(a[3]), "r"(b[0]), "r"(b[1]));
}
static __device__ __forceinline__ uint32 packsplit(float x0, float x1, uint32& lo) {
    __half h0 = __float2half_rn(x0), h1 = __float2half_rn(x1);
    __half l0 = __float2half_rn(x0 - __half2float(h0));
    __half l1 = __float2half_rn(x1 - __half2float(h1));
    lo = (uint32)__half_as_ushort(l0) | ((uint32)__half_as_ushort(l1) << 16);
    return (uint32)__half_as_ushort(h0) | ((uint32)__half_as_ushort(h1) << 16);
}

// ---------------- prep: vectorized weight quantize (8 k's -> one uint4 store) ----------------
static __device__ __forceinline__ void st8(uint4* tiles, int tilebytes, int tile,
                                           int nn, int kk8, const float* v, int stride) {
    ush h[8];
#pragma unroll
    for (int j = 0; j < 8; ++j) h[j] = __half_as_ushort(__float2half_rn(v[j * stride]));
    uint4 pk;
    pk.x = (uint32)h[0] | ((uint32)h[1] << 16);
    pk.y = (uint32)h[2] | ((uint32)h[3] << 16);
    pk.z = (uint32)h[4] | ((uint32)h[5] << 16);
    pk.w = (uint32)h[6] | ((uint32)h[7] << 16);
    *(uint4*)((char*)tiles + (size_t)tile * tilebytes + nn * 64 + kk8 * 16) = pk;
}

__global__ void prep_kernel(const float* __restrict__ w1, const float* __restrict__ w2,
                            const float* __restrict__ w3, const float* __restrict__ wpo1,
                            const float* __restrict__ wv1, const float* __restrict__ wfc,
                            const float* __restrict__ bpo1, const float* __restrict__ bv1) {
    int i = blockIdx.x * blockDim.x + threadIdx.x;
    if (i < 768) {   // conv1: k = c*64+ks contiguous in w1 row
        int oc = i / 24, kv = i - oc * 24, k0 = kv * 8;
        st8(g_w1sw, 2048, k0 >> 5, oc, (k0 & 31) >> 3, w1 + oc * 192 + k0, 1);
    }
    if (i < 4096) {  // conv2: k = ks*32+c; src w2[oc*512 + c*16 + ks]
        int oc = i & 63, kv = i >> 6, k0 = kv * 8;
        int ks = k0 >> 5, c0 = k0 & 31;
        st8(g_w2sw, 4096, ks, oc, c0 >> 3, w2 + oc * 512 + c0 * 16 + ks, 16);
    }
    if (i < 4608) {  // conv3: tile = ks*2+(c>>5); src w3[oc*576 + c*9 + ks]
        int oc = i / 72, kv = i - oc * 72;
        int ks = kv >> 3, c0 = (kv & 7) * 8;
        st8(g_w3sw, 4096, ks * 2 + (c0 >> 5), oc, (c0 & 31) >> 3, w3 + oc * 576 + c0 * 9 + ks, 9);
    }
    if (i < 132096) { // policy/value concat: src stride 64 over k
        int kv = i >> 7, n = i & 127, k0 = kv * 8;
        const float* src = (n < 64) ? (wpo1 + (size_t)k0 * 64 + n)
                                    : (wv1 + (size_t)k0 * 64 + (n - 64));
        st8(g_wposw, 4096, (n >> 6) * 258 + (k0 >> 5), n & 63, (k0 & 31) >> 3, src, 64);
    }
    if (i < 200704) { // FC: k=p*64+c; src wfc[(c*49+p)*512 + n], stride 49*512 over c
        int kv = i >> 9, n = i & 511, k0 = kv * 8;
        int p = k0 >> 6, c0 = k0 & 63;
        st8(g_wfcsw, 4096, (n >> 6) * 98 + p * 2 + (c0 >> 5), n & 63, (c0 & 31) >> 3,
            wfc + ((size_t)c0 * 49 + p) * 512 + n, 49 * 512);
    }
    if (i < 128) g_bcat[i] = (i < 64) ? bpo1[i] : bv1[i - 64];
}

// ---------------- image -> planar fp16 hi/lo, smem-coalesced (fused /255) ----------------
__global__ void __launch_bounds__(256) imgprep_kernel(const float* __restrict__ img) {
    extern __shared__ float spix[];          // 21168 floats (one image)
    const int n = blockIdx.x, tid = threadIdx.x;
    const float4* src = (const float4*)(img + (size_t)n * 21168);
    for (int i = tid; i < 5292; i += 256) ((float4*)spix)[i] = src[i];
    __syncthreads();
#pragma unroll
    for (int c = 0; c < 3; ++c) {
        size_t ob = ((size_t)n * 3 + c) * 7056;
        for (int pp = tid; pp < 3528; pp += 256) {
            float v0 = spix[(pp * 2) * 3 + c] * (1.f / 255.f);
            float v1 = spix[(pp * 2 + 1) * 3 + c] * (1.f / 255.f);
            uint32 lo, hi = packsplit(v0, v1, lo);
            *(uint32*)(g_imgh + ob + pp * 2) = hi;
            *(uint32*)(g_imgl + ob + pp * 2) = lo;
        }
    }
}

// ---------------- depth-3 pipelined mma.sync GEMM, fp16 exact-A x fp16-B ----------------
// BM=128, BN=NT, BK=32 chunks, 256 threads (8 warps: 4M x 2N), 80B rows, triple buffer.
// MODE 0: direct [gm][lda]; 1: conv2 gather; 2: conv3 gather; 3: conv1 planar (B-resident).
template<int MODE, int NT>
__global__ void __launch_bounds__(256, 2) gemmP(
    const ush* __restrict__ Ah, const ush* __restrict__ Al, int lda,
    const uint4* __restrict__ Bt, int qtotal, int qsplit,
    float* __restrict__ Cf, ush* __restrict__ Ch, ush* __restrict__ Cl,
    int ldc, int Mtotal, const float* __restrict__ bias, int dorelu)
{
    constexpr bool BRES = (MODE == 3);
    constexpr int MI = 2;
    constexpr int NI = NT / 16;
    constexpr int APLANE = 128 * 80;        // 10240
    constexpr int ABYTES = 2 * APLANE;      // 20480
    constexpr int BSM = NT * 80;
    constexpr int BUFSZ = ABYTES + (BRES ? 0 : BSM);
    extern __shared__ __align__(16) char smem[];
    const uint32 sb = s2u(smem);
    const uint32 Bres = sb + 3 * BUFSZ;     // B-resident region (MODE 3 only)
    const int tid = threadIdx.x;
    const int mtile = blockIdx.y, ntile = blockIdx.x, z = blockIdx.z;
    if (Cf) Cf += (size_t)z * Mtotal * ldc;

    const int arow = tid & 127, ahalf = tid >> 7;
    const int gm = mtile * 128 + arow;
    size_t abase = 0; int oy = 0, ox = 0;
    if (MODE == 0) abase = (size_t)gm * lda;
    else if (MODE == 1) { int n = gm / 81, p = gm - n * 81; oy = (p / 9) * 2; ox = (p % 9) * 2; abase = (size_t)n * 12800; }
    else if (MODE == 2) { int n = gm / 49, p = gm - n * 49; oy = p / 7; ox = p - oy * 7; abase = (size_t)n * 5184; }
    else { int n = gm / 400, p = gm - n * 400; oy = p / 20; ox = p - oy * 20; abase = (size_t)n * 21168; }

    const int qb = z * qsplit;
    const int qe = min(qtotal, qb + qsplit);

    auto stage = [&](int q, int buf) {
        uint32 Ab = sb + buf * BUFSZ;
        uint32 rowb = Ab + arow * 80;
        if (MODE == 3) {
            size_t base = abase + (size_t)(q >> 1) * 7056
                        + (size_t)(oy * 4 + (q & 1) * 4 + ahalf * 2) * 84 + ox * 4;
#pragma unroll
            for (int j = 0; j < 2; ++j) {
                const char* gh = (const char*)(Ah + base + j * 84);
                const char* gl = (const char*)(Al + base + j * 84);
                uint32 d = rowb + (ahalf * 2 + j) * 16;
                cpa8(d, gh); cpa8(d + 8, gh + 8);
                cpa8(d + APLANE, gl); cpa8(d + APLANE + 8, gl + 8);
            }
        } else {
            size_t off;
            if (MODE == 0) off = abase + (size_t)q * 32;
            else if (MODE == 1) {
                off = abase + (size_t)((oy + (q >> 2)) * 20 + ox + (q & 3)) * 32;
            } else {
                int ks = q >> 1;
                int ky = ks / 3, kx = ks - ky * 3;
                off = abase + (size_t)((oy + ky) * 9 + ox + kx) * 64 + (q & 1) * 32;
            }
            off += ahalf * 16;
            const char* gh = (const char*)(Ah + off);
            const char* gl = (const char*)(Al + off);
            uint32 d = rowb + ahalf * 32;
            cpa16(d, gh); cpa16(d + 16, gh + 16);
            cpa16(d + APLANE, gl); cpa16(d + APLANE + 16, gl + 16);
        }
        if (!BRES) {
            uint32 Bb = Ab + ABYTES;
            const uint4* bt = Bt + (size_t)(ntile * qtotal + q) * (NT * 4);
            for (int e = tid; e < NT * 4; e += 256)
                cpa16(Bb + (e >> 2) * 80 + (e & 3) * 16, bt + e);
        }
        asm volatile("cp.async.commit_group;" ::: "memory");
    };

    const int wid = tid >> 5, L = tid & 31;
    const int warpM = (wid & 3) * 32;
    const int warpN = (wid >> 2) * (NI * 8);
    const int arow0 = warpM + (L & 7) + ((L >> 3) & 1) * 8;
    const int asegh = (L >> 4) & 1;
    const int brow0 = warpN + (L & 7);
    const int bsegh = (L >> 3) & 1;

    float acc[MI][NI][4];
#pragma unroll
    for (int mi = 0; mi < MI; ++mi)
#pragma unroll
        for (int ni = 0; ni < NI; ++ni)
#pragma unroll
            for (int r = 0; r < 4; ++r) acc[mi][ni][r] = 0.f;

    if (BRES) {
        const uint4* bt = Bt + (size_t)(ntile * qtotal + qb) * (NT * 4);
        const int total = (qe - qb) * (NT * 4);
        for (int e = tid; e < total; e += 256) {
            int ch = e / (NT * 4), r = e - ch * (NT * 4);
            cpa16(Bres + ch * BSM + (r >> 2) * 80 + (r & 3) * 16, bt + e);
        }
    }
    stage(qb, 0);
    if (qb + 1 < qe) stage(qb + 1, 1);

    for (int q = qb; q < qe; ++q) {
        int cb = (q - qb) % 3;
        if (q + 1 < qe)
            asm volatile("cp.async.wait_group 1;" ::: "memory");
        else
            asm volatile("cp.async.wait_group 0;" ::: "memory");
        __syncthreads();
        if (q + 2 < qe) stage(q + 2, (cb + 2) % 3);
        uint32 Ab = sb + cb * BUFSZ;
        uint32 Bb = BRES ? (Bres + (q - qb) * BSM) : (Ab + ABYTES);
#pragma unroll
        for (int g = 0; g < 2; ++g) {        // two k16 groups per 32-K chunk
            uint32 bh[NI][2];
#pragma unroll
            for (int ni = 0; ni < NI; ++ni)
                ldsm2(Bb + (brow0 + ni * 8) * 80 + g * 32 + bsegh * 16, bh[ni]);
#pragma unroll
            for (int mi = 0; mi < MI; ++mi) {
                int row = arow0 + mi * 16;
                uint32 ad = Ab + row * 80 + g * 32 + asegh * 16;
                uint32 a[4];
                ldsm4(ad, a);                 // hi plane
#pragma unroll
                for (int ni = 0; ni < NI; ++ni) mmaF16(acc[mi][ni], a, bh[ni]);
                ldsm4(ad + APLANE, a);        // lo plane (reuse regs)
#pragma unroll
                for (int ni = 0; ni < NI; ++ni) mmaF16(acc[mi][ni], a, bh[ni]);
            }
        }
    }

    // ---- epilogue ----
    const int gID = L >> 2, tg = L & 3;
#pragma unroll
    for (int mi = 0; mi < MI; ++mi)
#pragma unroll
        for (int ni = 0; ni < NI; ++ni) {
            int m = mtile * 128 + warpM + mi * 16 + gID;
            int col = ntile * NT + warpN + ni * 8 + tg * 2;
            float x0 = acc[mi][ni][0], x1 = acc[mi][ni][1];
            float x2 = acc[mi][ni][2], x3 = acc[mi][ni][3];
            if (bias) {
                float2 bb = *(const float2*)(bias + col);
                x0 += bb.x; x1 += bb.y; x2 += bb.x; x3 += bb.y;
            }
            if (dorelu) {
                x0 = fmaxf(x0, 0.f); x1 = fmaxf(x1, 0.f);
                x2 = fmaxf(x2, 0.f); x3 = fmaxf(x3, 0.f);
            }
            if (Cf) {
                *(float2*)(Cf + (size_t)m * ldc + col) = make_float2(x0, x1);
                *(float2*)(Cf + (size_t)(m + 8) * ldc + col) = make_float2(x2, x3);
            } else {
                uint32 lo, hi;
                hi = packsplit(x0, x1, lo);
                *(uint32*)(Ch + (size_t)m * ldc + col) = hi;
                *(uint32*)(Cl + (size_t)m * ldc + col) = lo;
                hi = packsplit(x2, x3, lo);
                *(uint32*)(Ch + (size_t)(m + 8) * ldc + col) = hi;
                *(uint32*)(Cl + (size_t)(m + 8) * ldc + col) = lo;
            }
        }
}

// ---------------- split-K reduce + bias + relu ----------------
__global__ void reduce_kernel(const float* __restrict__ bias, float* __restrict__ outp,
                              int N, int nparts, int stride, int count, int dorelu) {
    int i = blockIdx.x * blockDim.x + threadIdx.x;
    if (i >= count) return;
    float s = 0.f;
    for (int ss = 0; ss < nparts; ++ss) s += g_part[(size_t)ss * stride + i];
    s += bias[i % N];
    outp[i] = dorelu ? fmaxf(s, 0.f) : s;
}

// ---------------- wfeat = g_h @ Ww + bw ----------------
__global__ void __launch_bounds__(256) wfeat_kernel(const float* __restrict__ Ww,
                                                    const float* __restrict__ bw) {
    int t = blockIdx.x * 256 + threadIdx.x;
    int n = t >> 5, oc = t & 31;
    const float* hrow = g_h + (size_t)n * 512;
    float s = bw[oc];
#pragma unroll 8
    for (int k = 0; k < 512; ++k) s += hrow[k] * Ww[k * 32 + oc];
    g_wfeat[t] = s;
}

// ---------------- sequential scan: writes hidden planes + fp32 state ----------------
__global__ void __launch_bounds__(256) scan_kernel(const float* __restrict__ done,
                                                   const float* __restrict__ state0,
                                                   const int* __restrict__ position,
                                                   float* __restrict__ out_state) {
    const int b = blockIdx.x, cq = blockIdx.y * 2, j = threadIdx.x;
    float st[2];
#pragma unroll
    for (int c = 0; c < 2; ++c) st[c] = state0[b * 8192 + (cq + c) * 256 + j];
    for (int t = 0; t < 32; ++t) {
        int idx = t * 64 + b;
        float m = 1.0f - done[idx];
#pragma unroll
        for (int c = 0; c < 2; ++c) st[c] *= m;
        int p0 = position[idx * 2], p1 = position[idx * 2 + 1];
        if (j == p0 * 16 + p1) {
#pragma unroll
            for (int c = 0; c < 2; ++c) st[c] += g_wfeat[idx * 32 + cq + c];
        }
        size_t rb = (size_t)idx * 8256;
#pragma unroll
        for (int c = 0; c < 2; ++c) {
            __half h = __float2half_rn(st[c]);
            g_hidh[rb + (cq + c) * 256 + j] = __half_as_ushort(h);
            g_hidl[rb + (cq + c) * 256 + j] =
                __half_as_ushort(__float2half_rn(st[c] - __half2float(h)));
        }
    }
#pragma unroll
    for (int c = 0; c < 2; ++c) out_state[b * 8192 + (cq + c) * 256 + j] = st[c];
}

// ---------------- pos_net -> hidden plane cols 8192..8255 ----------------
__global__ void __launch_bounds__(64) posnet_kernel(const int* __restrict__ position,
                                                    const float* __restrict__ wp1,
                                                    const float* __restrict__ bp1,
                                                    const float* __restrict__ wp2,
                                                    const float* __restrict__ bp2) {
    __shared__ float hr[64];
    const int n = blockIdx.x, k = threadIdx.x;
    int p0 = position[n * 2], p1 = position[n * 2 + 1];
    hr[k] = fmaxf(wp1[p0 * 64 + k] + wp1[(16 + p1) * 64 + k] + bp1[k], 0.f);
    __syncthreads();
    float s = bp2[k];
#pragma unroll 8
    for (int j = 0; j < 64; ++j) s += hr[j] * wp2[j * 64 + k];
    __half h = __float2half_rn(s);
    g_hidh[(size_t)n * 8256 + 8192 + k] = __half_as_ushort(h);
    g_hidl[(size_t)n * 8256 + 8192 + k] =
        __half_as_ushort(__float2half_rn(s - __half2float(h)));
}

// ---------------- heads ----------------
__global__ void heads_kernel(const float* __restrict__ wpo2, const float* __restrict__ bpo2,
                             const float* __restrict__ wv2, const float* __restrict__ bv2,
                             float* __restrict__ out_logits, float* __restrict__ out_v) {
    int n = blockIdx.x * blockDim.x + threadIdx.x;
    if (n >= 2048) return;
    const float* z = g_z + (size_t)n * 128;
    float lg[5];
#pragma unroll
    for (int a = 0; a < 5; ++a) lg[a] = bpo2[a];
    float vv = bv2[0];
#pragma unroll 4
    for (int j = 0; j < 64; ++j) {
        float zj = z[j];
#pragma unroll
        for (int a = 0; a < 5; ++a) lg[a] += zj * wpo2[j * 5 + a];
        vv += z[64 + j] * wv2[j];
    }
#pragma unroll
    for (int a = 0; a < 5; ++a) out_logits[n * 5 + a] = lg[a];
    out_v[n] = vv;
}

// ---------------- launch ----------------
extern "C" void kernel_launch(void* const* d_in, const int* in_sizes, int n_in,
                              void* d_out, int out_size) {
    bool dict_order = (in_sizes[3] == 4096 && in_sizes[4] == 6144);
    int wb = dict_order ? 4 : 3;
    int posIdx = dict_order ? 3 : 25;

    const float* image  = (const float*)d_in[0];
    const float* done   = (const float*)d_in[1];
    const float* state0 = (const float*)d_in[2];
    const int*   position = (const int*)d_in[posIdx];
    const float* w1  = (const float*)d_in[wb + 0];
    const float* b1  = (const float*)d_in[wb + 1];
    const float* w2  = (const float*)d_in[wb + 2];
    const float* b2  = (const float*)d_in[wb + 3];
    const float* w3  = (const float*)d_in[wb + 4];
    const float* b3  = (const float*)d_in[wb + 5];
    const float* wfc = (const float*)d_in[wb + 6];
    const float* bfc = (const float*)d_in[wb + 7];
    const float* Ww  = (const float*)d_in[wb + 8];
    const float* bw  = (const float*)d_in[wb + 9];
    const float* wp1 = (const float*)d_in[wb + 10];
    const float* bp1 = (const float*)d_in[wb + 11];
    const float* wp2 = (const float*)d_in[wb + 12];
    const float* bp2 = (const float*)d_in[wb + 13];
    const float* wpo1 = (const float*)d_in[wb + 14];
    const float* bpo1 = (const float*)d_in[wb + 15];
    const float* wpo2 = (const float*)d_in[wb + 16];
    const float* bpo2 = (const float*)d_in[wb + 17];
    const float* wv1 = (const float*)d_in[wb + 18];
    const float* bv1 = (const float*)d_in[wb + 19];
    const float* wv2 = (const float*)d_in[wb + 20];
    const float* bv2 = (const float*)d_in[wb + 21];

    float* out = (float*)d_out;
    float* out_logits = out;
    float* out_v      = out + 10240;
    float* out_state  = out + 12288;

    ush *p_imgh, *p_imgl, *p_a1h, *p_a1l, *p_a2h, *p_a2l, *p_a3h, *p_a3l, *p_hidh, *p_hidl;
    float *p_h, *p_part, *p_z, *p_bcat;
    uint4 *p_w1sw, *p_w2sw, *p_w3sw, *p_wfcsw, *p_wposw;
    cudaGetSymbolAddress((void**)&p_imgh, g_imgh);
    cudaGetSymbolAddress((void**)&p_imgl, g_imgl);
    cudaGetSymbolAddress((void**)&p_a1h, g_a1h);
    cudaGetSymbolAddress((void**)&p_a1l, g_a1l);
    cudaGetSymbolAddress((void**)&p_a2h, g_a2h);
    cudaGetSymbolAddress((void**)&p_a2l, g_a2l);
    cudaGetSymbolAddress((void**)&p_a3h, g_a3h);
    cudaGetSymbolAddress((void**)&p_a3l, g_a3l);
    cudaGetSymbolAddress((void**)&p_hidh, g_hidh);
    cudaGetSymbolAddress((void**)&p_hidl, g_hidl);
    cudaGetSymbolAddress((void**)&p_h, g_h);
    cudaGetSymbolAddress((void**)&p_part, g_part);
    cudaGetSymbolAddress((void**)&p_z, g_z);
    cudaGetSymbolAddress((void**)&p_bcat, g_bcat);
    cudaGetSymbolAddress((void**)&p_w1sw, g_w1sw);
    cudaGetSymbolAddress((void**)&p_w2sw, g_w2sw);
    cudaGetSymbolAddress((void**)&p_w3sw, g_w3sw);
    cudaGetSymbolAddress((void**)&p_wfcsw, g_wfcsw);
    cudaGetSymbolAddress((void**)&p_wposw, g_wposw);

    const int SM64 = 3 * (20480 + 64 * 80);        // 76800
    const int SM1  = 3 * 20480 + 6 * (32 * 80);    // 76800 (conv1: A triple-buf + resident B)
    const int SMIMG = 21168 * 4;                   // 84672
    cudaFuncSetAttribute(imgprep_kernel, cudaFuncAttributeMaxDynamicSharedMemorySize, SMIMG);
    cudaFuncSetAttribute(gemmP<3,32>, cudaFuncAttributeMaxDynamicSharedMemorySize, SM1);
    cudaFuncSetAttribute(gemmP<1,64>, cudaFuncAttributeMaxDynamicSharedMemorySize, SM64);
    cudaFuncSetAttribute(gemmP<2,64>, cudaFuncAttributeMaxDynamicSharedMemorySize, SM64);
    cudaFuncSetAttribute(gemmP<0,64>, cudaFuncAttributeMaxDynamicSharedMemorySize, SM64);

    prep_kernel<<<392, 512>>>(w1, w2, w3, wpo1, wv1, wfc, bpo1, bv1);
    imgprep_kernel<<<2048, 256, SMIMG>>>(image);
    // conv1: M=819200, N=32, K=192 (6 chunks of 32, channel-planar, B-resident)
    gemmP<3,32><<<dim3(1, 6400, 1), 256, SM1>>>(p_imgh, p_imgl, 0, p_w1sw, 6, 6,
                                                (float*)0, p_a1h, p_a1l, 32, 819200, b1, 1);
    // conv2: M=165888, N=64, K=512 (16 chunks)
    gemmP<1,64><<<dim3(1, 1296, 1), 256, SM64>>>(p_a1h, p_a1l, 0, p_w2sw, 16, 16,
                                                 (float*)0, p_a2h, p_a2l, 64, 165888, b2, 1);
    // conv3: M=100352, N=64, K=576 (18 chunks)
    gemmP<2,64><<<dim3(1, 784, 1), 256, SM64>>>(p_a2h, p_a2l, 0, p_w3sw, 18, 18,
                                                (float*)0, p_a3h, p_a3l, 64, 100352, b3, 1);
    // FC: M=2048, N=512 (8 ntiles), K=3136 (98 chunks), split-K=2
    gemmP<0,64><<<dim3(8, 16, 2), 256, SM64>>>(p_a3h, p_a3l, 3136, p_wfcsw, 98, 49,
                                               p_part, (ush*)0, (ush*)0, 512, 2048,
                                               (const float*)0, 0);
    reduce_kernel<<<2048, 512>>>(bfc, p_h, 512, 2, 2048 * 512, 2048 * 512, 1);
    wfeat_kernel<<<256, 256>>>(Ww, bw);
    scan_kernel<<<dim3(64, 16, 1), 256>>>(done, state0, position, out_state);
    posnet_kernel<<<2048, 64>>>(position, wp1, bp1, wp2, bp2);
    // policy/value: M=2048, N=128 (2 ntiles), K=8256 (258 chunks), split-K=8
    gemmP<0,64><<<dim3(2, 16, 8), 256, SM64>>>(p_hidh, p_hidl, 8256, p_wposw, 258, 33,
                                               p_part, (ush*)0, (ush*)0, 128, 2048,
                                               (const float*)0, 0);
    reduce_kernel<<<512, 512>>>(p_bcat, p_z, 128, 8, 2048 * 128, 2048 * 128, 1);
    heads_kernel<<<16, 128>>>(wpo2, bpo2, wv2, bv2, out_logits, out_v);
}

// round 15
// speedup vs baseline: 1.1016x; 1.1016x over previous
#include <cuda_runtime.h>
#include <cuda_fp16.h>
#include <cstdint>

typedef unsigned short ush;
typedef unsigned int uint32;

// ---------------- scratch (device globals; zero-initialized, no allocation) ----------------
__device__ ush g_imgh[2048 * 3 * 7056];   // image fp16 hi, planar [n][c][y*84+x]
__device__ ush g_imgl[2048 * 3 * 7056];
__device__ ush g_a1h[2048 * 400 * 32];    // conv1 out planes [n*400+p][32]
__device__ ush g_a1l[2048 * 400 * 32];
__device__ ush g_a2h[2048 * 81 * 64];     // conv2 out planes
__device__ ush g_a2l[2048 * 81 * 64];
__device__ ush g_a3h[2048 * 49 * 64];     // conv3 out planes [n*49+p][64]
__device__ ush g_a3l[2048 * 49 * 64];
__device__ ush g_hidh[2048 * 8256];       // hidden planes [map 8192 | pos 64]
__device__ ush g_hidl[2048 * 8256];
__device__ float g_h[2048 * 512];
__device__ float g_wfeat[2048 * 32];
__device__ float g_part[2 * 2048 * 512];
__device__ float g_z[2048 * 128];
__device__ float g_bcat[128];
// fp16 weight tiles (hi only), packed rows: chunk tile = NT rows x 64 bytes (32 k's).
__device__ uint4 g_w1sw[6 * 128];         // conv1: 6 chunks x 2KB (NT=32)
__device__ uint4 g_w2sw[16 * 256];        // conv2: 16 chunks x 4KB
__device__ uint4 g_w3sw[18 * 256];        // conv3: 18 chunks
__device__ uint4 g_wfcsw[8 * 98 * 256];   // FC: 8 ntiles x 98 chunks
__device__ uint4 g_wposw[2 * 258 * 256];  // policy: 2 ntiles x 258 chunks

// ---------------- helpers ----------------
static __device__ __forceinline__ uint32 s2u(const void* p) {
    uint32 a;
    asm("{ .reg .u64 t; cvta.to.shared.u64 t, %1; cvt.u32.u64 %0, t; }" : "=r"(a) : "l"(p));
    return a;
}
static __device__ __forceinline__ void cpa16(uint32 d, const void* s) {
    asm volatile("cp.async.cg.shared.global [%0], [%1], 16;" :: "r"(d), "l"(s));
}
static __device__ __forceinline__ void cpa8(uint32 d, const void* s) {
    asm volatile("cp.async.ca.shared.global [%0], [%1], 8;" :: "r"(d), "l"(s));
}
static __device__ __forceinline__ void ldsm4(uint32 addr, uint32* r) {
    asm volatile("ldmatrix.sync.aligned.m8n8.x4.shared.b16 {%0,%1,%2,%3}, [%4];"
                 : "=r"(r[0]), "=r"(r[1]), "=r"(r[2]), "=r"(r[3]) : "r"(addr));
}
static __device__ __forceinline__ void ldsm2(uint32 addr, uint32* r) {
    asm volatile("ldmatrix.sync.aligned.m8n8.x2.shared.b16 {%0,%1}, [%2];"
                 : "=r"(r[0]), "=r"(r[1]) : "r"(addr));
}
static __device__ __forceinline__ void mmaF16(float* c, const uint32* a, const uint32* b) {
    asm volatile(
        "mma.sync.aligned.m16n8k16.row.col.f32.f16.f16.f32 "
        "{%0,%1,%2,%3}, {%4,%5,%6,%7}, {%8,%9}, {%0,%1,%2,%3};"
        : "+f"(c[0]), "+f"(c[1]), "+f"(c[2]), "+f"(c[3])
        : "r"(a[0]), "r"(a[1]), "r"(a[2]), "r"(a[3]), "r"(b[0]), "r"(b[1]));
}
static __device__ __forceinline__ uint32 packsplit(float x0, float x1, uint32& lo) {
    __half h0 = __float2half_rn(x0), h1 = __float2half_rn(x1);
    __half l0 = __float2half_rn(x0 - __half2float(h0));
    __half l1 = __float2half_rn(x1 - __half2float(h1));
    lo = (uint32)__half_as_ushort(l0) | ((uint32)__half_as_ushort(l1) << 16);
    return (uint32)__half_as_ushort(h0) | ((uint32)__half_as_ushort(h1) << 16);
}

// ---------------- prep: vectorized weight quantize (8 k's -> one uint4 store) ----------------
static __device__ __forceinline__ void st8(uint4* tiles, int tilebytes, int tile,
                                           int nn, int kk8, const float* v, int stride) {
    ush h[8];
#pragma unroll
    for (int j = 0; j < 8; ++j) h[j] = __half_as_ushort(__float2half_rn(v[j * stride]));
    uint4 pk;
    pk.x = (uint32)h[0] | ((uint32)h[1] << 16);
    pk.y = (uint32)h[2] | ((uint32)h[3] << 16);
    pk.z = (uint32)h[4] | ((uint32)h[5] << 16);
    pk.w = (uint32)h[6] | ((uint32)h[7] << 16);
    *(uint4*)((char*)tiles + (size_t)tile * tilebytes + nn * 64 + kk8 * 16) = pk;
}

__global__ void prep_kernel(const float* __restrict__ w1, const float* __restrict__ w2,
                            const float* __restrict__ w3, const float* __restrict__ wpo1,
                            const float* __restrict__ wv1, const float* __restrict__ wfc,
                            const float* __restrict__ bpo1, const float* __restrict__ bv1) {
    int i = blockIdx.x * blockDim.x + threadIdx.x;
    if (i < 768) {   // conv1: k = c*64+ks contiguous in w1 row
        int oc = i / 24, kv = i - oc * 24, k0 = kv * 8;
        st8(g_w1sw, 2048, k0 >> 5, oc, (k0 & 31) >> 3, w1 + oc * 192 + k0, 1);
    }
    if (i < 4096) {  // conv2: k = ks*32+c; src w2[oc*512 + c*16 + ks]
        int oc = i & 63, kv = i >> 6, k0 = kv * 8;
        int ks = k0 >> 5, c0 = k0 & 31;
        st8(g_w2sw, 4096, ks, oc, c0 >> 3, w2 + oc * 512 + c0 * 16 + ks, 16);
    }
    if (i < 4608) {  // conv3: tile = ks*2+(c>>5); src w3[oc*576 + c*9 + ks]
        int oc = i / 72, kv = i - oc * 72;
        int ks = kv >> 3, c0 = (kv & 7) * 8;
        st8(g_w3sw, 4096, ks * 2 + (c0 >> 5), oc, (c0 & 31) >> 3, w3 + oc * 576 + c0 * 9 + ks, 9);
    }
    if (i < 132096) { // policy/value concat: src stride 64 over k
        int kv = i >> 7, n = i & 127, k0 = kv * 8;
        const float* src = (n < 64) ? (wpo1 + (size_t)k0 * 64 + n)
                                    : (wv1 + (size_t)k0 * 64 + (n - 64));
        st8(g_wposw, 4096, (n >> 6) * 258 + (k0 >> 5), n & 63, (k0 & 31) >> 3, src, 64);
    }
    if (i < 200704) { // FC: k=p*64+c; src wfc[(c*49+p)*512 + n]
        int kv = i >> 9, n = i & 511, k0 = kv * 8;
        int p = k0 >> 6, c0 = k0 & 63;
        st8(g_wfcsw, 4096, (n >> 6) * 98 + p * 2 + (c0 >> 5), n & 63, (c0 & 31) >> 3,
            wfc + ((size_t)c0 * 49 + p) * 512 + n, 49 * 512);
    }
    if (i < 128) g_bcat[i] = (i < 64) ? bpo1[i] : bv1[i - 64];
}

// ---------------- image -> planar fp16 hi/lo, smem-coalesced (fused /255) ----------------
__global__ void __launch_bounds__(256) imgprep_kernel(const float* __restrict__ img) {
    extern __shared__ float spix[];
    const int n = blockIdx.x, tid = threadIdx.x;
    const float4* src = (const float4*)(img + (size_t)n * 21168);
    for (int i = tid; i < 5292; i += 256) ((float4*)spix)[i] = src[i];
    __syncthreads();
#pragma unroll
    for (int c = 0; c < 3; ++c) {
        size_t ob = ((size_t)n * 3 + c) * 7056;
        for (int pp = tid; pp < 3528; pp += 256) {
            float v0 = spix[(pp * 2) * 3 + c] * (1.f / 255.f);
            float v1 = spix[(pp * 2 + 1) * 3 + c] * (1.f / 255.f);
            uint32 lo, hi = packsplit(v0, v1, lo);
            *(uint32*)(g_imgh + ob + pp * 2) = hi;
            *(uint32*)(g_imgl + ob + pp * 2) = lo;
        }
    }
}

// ================= image-resident conv GEMM (conv2 / conv3) =================
// Whole input image(s) resident in smem; per-lane-address ldmatrix gathers A.
// Only the 4KB B tile is staged per 32-K chunk (double-buffered).
template<int CONV>
__global__ void __launch_bounds__(CONV == 2 ? 192 : 256, 2) convR(
    const ush* __restrict__ Ah, const ush* __restrict__ Al,
    const uint4* __restrict__ Bt,
    ush* __restrict__ Ch, ush* __restrict__ Cl,
    const float* __restrict__ bias)
{
    constexpr int PSTR  = (CONV == 2) ? 80 : 144;     // padded bytes per pixel row
    constexpr int NPIX  = (CONV == 2) ? 400 : 81;
    constexpr int NIMG  = (CONV == 2) ? 1 : 2;
    constexpr int ROWB  = (CONV == 2) ? 64 : 128;     // data bytes per pixel row
    constexpr int IPLANE = NPIX * PSTR;               // per-image per-plane bytes
    constexpr int AHALF  = IPLANE * NIMG;             // hi region size
    constexpr int ATOT   = 2 * AHALF;
    constexpr int QTOT  = (CONV == 2) ? 16 : 18;
    constexpr int THR   = (CONV == 2) ? 192 : 256;
    constexpr int BSM   = 64 * 80;                    // 5120 per B buffer
    extern __shared__ __align__(16) char smem[];
    const uint32 sb = s2u(smem);
    const uint32 Bb0 = sb + ATOT;
    const int tid = threadIdx.x, blk = blockIdx.x;

    // ---- prologue: resident A (hi+lo) + B chunk 0, one commit group ----
    for (int r = tid; r < NPIX * NIMG; r += THR) {
        int img = r / NPIX, p = r - img * NPIX;
        const char* gh = (const char*)(Ah + ((size_t)(blk * NIMG + img) * NPIX + p) * (ROWB / 2));
        const char* gl = (const char*)(Al + ((size_t)(blk * NIMG + img) * NPIX + p) * (ROWB / 2));
        uint32 d = sb + img * IPLANE + p * PSTR;
#pragma unroll
        for (int s = 0; s < ROWB / 16; ++s) {
            cpa16(d + s * 16, gh + s * 16);
            cpa16(d + AHALF + s * 16, gl + s * 16);
        }
    }
    for (int e = tid; e < 256; e += THR)
        cpa16(Bb0 + (e >> 2) * 80 + (e & 3) * 16, Bt + e);
    asm volatile("cp.async.commit_group;" ::: "memory");

    // ---- lane geometry ----
    const int wid = tid >> 5, L = tid & 31;
    const int warpM = (CONV == 2) ? (wid % 3) * 32 : (wid & 3) * 32;
    const int warpN = (CONV == 2) ? (wid / 3) * 32 : (wid >> 2) * 32;
    const int t4 = L >> 3;
    const int mA0 = warpM + (t4 & 1) * 8 + (L & 7);
    const int kbyte = (t4 >> 1) * 16;
    uint32 aconst[2];
#pragma unroll
    for (int mi = 0; mi < 2; ++mi) {
        int m = mA0 + mi * 16;
        int img, row;
        if (CONV == 2) { img = 0; row = (m < 81) ? m : 0; }
        else { img = m >> 6; row = ((m & 63) < 49) ? (m & 63) : 0; }
        int pc;
        if (CONV == 2) { int oy = row / 9, ox = row - oy * 9; pc = (oy * 2 * 20 + ox * 2) * PSTR; }
        else { int oy = row / 7, ox = row - oy * 7; pc = (oy * 9 + ox) * PSTR; }
        aconst[mi] = sb + img * IPLANE + pc + kbyte;
    }
    const int brow0 = warpN + (L & 7);
    const int bsegh = (L >> 3) & 1;

    float acc[2][4][4];
#pragma unroll
    for (int mi = 0; mi < 2; ++mi)
#pragma unroll
        for (int ni = 0; ni < 4; ++ni)
#pragma unroll
            for (int r = 0; r < 4; ++r) acc[mi][ni][r] = 0.f;

    for (int q = 0; q < QTOT; ++q) {
        asm volatile("cp.async.wait_group 0;" ::: "memory");
        __syncthreads();
        if (q + 1 < QTOT) {
            const uint4* bt = Bt + (size_t)(q + 1) * 256;
            uint32 Bd = Bb0 + ((q + 1) & 1) * BSM;
            for (int e = tid; e < 256; e += THR)
                cpa16(Bd + (e >> 2) * 80 + (e & 3) * 16, bt + e);
            asm volatile("cp.async.commit_group;" ::: "memory");
        }
        uint32 coff;
        if (CONV == 2) { int ky = q >> 2, kx = q & 3; coff = (ky * 20 + kx) * PSTR; }
        else { int ks = q >> 1; int ky = ks / 3, kx = ks - ky * 3;
               coff = (ky * 9 + kx) * PSTR + (q & 1) * 64; }
        uint32 Bb = Bb0 + (q & 1) * BSM;
#pragma unroll
        for (int g = 0; g < 2; ++g) {
            uint32 bh[4][2];
#pragma unroll
            for (int ni = 0; ni < 4; ++ni)
                ldsm2(Bb + (brow0 + ni * 8) * 80 + g * 32 + bsegh * 16, bh[ni]);
#pragma unroll
            for (int mi = 0; mi < 2; ++mi) {
                uint32 ad = aconst[mi] + coff + g * 32;
                uint32 a[4];
                ldsm4(ad, a);                 // hi plane
#pragma unroll
                for (int ni = 0; ni < 4; ++ni) mmaF16(acc[mi][ni], a, bh[ni]);
                ldsm4(ad + AHALF, a);         // lo plane
#pragma unroll
                for (int ni = 0; ni < 4; ++ni) mmaF16(acc[mi][ni], a, bh[ni]);
            }
        }
    }

    // ---- epilogue ----
    const int gID = L >> 2, tg = L & 3;
#pragma unroll
    for (int mi = 0; mi < 2; ++mi)
#pragma unroll
        for (int ni = 0; ni < 4; ++ni) {
            int col = warpN + ni * 8 + tg * 2;
#pragma unroll
            for (int half = 0; half < 2; ++half) {
                int m = warpM + mi * 16 + gID + half * 8;
                float x0 = acc[mi][ni][half * 2], x1 = acc[mi][ni][half * 2 + 1];
                int img, row, valid;
                if (CONV == 2) { img = 0; row = m; valid = (m < 81); }
                else { img = m >> 6; row = m & 63; valid = (row < 49); }
                if (!valid) continue;
                float2 bb = *(const float2*)(bias + col);
                x0 = fmaxf(x0 + bb.x, 0.f);
                x1 = fmaxf(x1 + bb.y, 0.f);
                uint32 lo, hi = packsplit(x0, x1, lo);
                size_t o = ((size_t)(blk * NIMG + img) * ((CONV == 2) ? 81 : 49) + row) * 64 + col;
                *(uint32*)(Ch + o) = hi;
                *(uint32*)(Cl + o) = lo;
            }
        }
}

// ---------------- depth-2 pipelined mma.sync GEMM (MODE 0 direct, MODE 3 conv1) ----------------
template<int MODE, int NT>
__global__ void __launch_bounds__(256, 3) gemmP(
    const ush* __restrict__ Ah, const ush* __restrict__ Al, int lda,
    const uint4* __restrict__ Bt, int qtotal, int qsplit,
    float* __restrict__ Cf, ush* __restrict__ Ch, ush* __restrict__ Cl,
    int ldc, int Mtotal, const float* __restrict__ bias, int dorelu)
{
    constexpr bool BRES = (MODE == 3);
    constexpr int MI = 2;
    constexpr int NI = NT / 16;
    constexpr int APLANE = 128 * 80;
    constexpr int ABYTES = 2 * APLANE;
    constexpr int BSM = NT * 80;
    constexpr int BUFSZ = ABYTES + (BRES ? 0 : BSM);
    extern __shared__ __align__(16) char smem[];
    const uint32 sb = s2u(smem);
    const uint32 Bres = sb + 2 * BUFSZ;
    const int tid = threadIdx.x;
    const int mtile = blockIdx.y, ntile = blockIdx.x, z = blockIdx.z;
    if (Cf) Cf += (size_t)z * Mtotal * ldc;

    const int arow = tid & 127, ahalf = tid >> 7;
    const int gm = mtile * 128 + arow;
    size_t abase = 0; int oy = 0, ox = 0;
    if (MODE == 0) abase = (size_t)gm * lda;
    else { int n = gm / 400, p = gm - n * 400; oy = p / 20; ox = p - oy * 20; abase = (size_t)n * 21168; }

    const int qb = z * qsplit;
    const int qe = min(qtotal, qb + qsplit);

    auto stage = [&](int q, int buf) {
        uint32 Ab = sb + buf * BUFSZ;
        uint32 rowb = Ab + arow * 80;
        if (MODE == 3) {
            size_t base = abase + (size_t)(q >> 1) * 7056
                        + (size_t)(oy * 4 + (q & 1) * 4 + ahalf * 2) * 84 + ox * 4;
#pragma unroll
            for (int j = 0; j < 2; ++j) {
                const char* gh = (const char*)(Ah + base + j * 84);
                const char* gl = (const char*)(Al + base + j * 84);
                uint32 d = rowb + (ahalf * 2 + j) * 16;
                cpa8(d, gh); cpa8(d + 8, gh + 8);
                cpa8(d + APLANE, gl); cpa8(d + APLANE + 8, gl + 8);
            }
        } else {
            size_t off = abase + (size_t)q * 32 + ahalf * 16;
            const char* gh = (const char*)(Ah + off);
            const char* gl = (const char*)(Al + off);
            uint32 d = rowb + ahalf * 32;
            cpa16(d, gh); cpa16(d + 16, gh + 16);
            cpa16(d + APLANE, gl); cpa16(d + APLANE + 16, gl + 16);
        }
        if (!BRES) {
            uint32 Bb = Ab + ABYTES;
            const uint4* bt = Bt + (size_t)(ntile * qtotal + q) * (NT * 4);
            for (int e = tid; e < NT * 4; e += 256)
                cpa16(Bb + (e >> 2) * 80 + (e & 3) * 16, bt + e);
        }
        asm volatile("cp.async.commit_group;" ::: "memory");
    };

    const int wid = tid >> 5, L = tid & 31;
    const int warpM = (wid & 3) * 32;
    const int warpN = (wid >> 2) * (NI * 8);
    const int arow0 = warpM + (L & 7) + ((L >> 3) & 1) * 8;
    const int asegh = (L >> 4) & 1;
    const int brow0 = warpN + (L & 7);
    const int bsegh = (L >> 3) & 1;

    float acc[MI][NI][4];
#pragma unroll
    for (int mi = 0; mi < MI; ++mi)
#pragma unroll
        for (int ni = 0; ni < NI; ++ni)
#pragma unroll
            for (int r = 0; r < 4; ++r) acc[mi][ni][r] = 0.f;

    if (BRES) {
        const uint4* bt = Bt + (size_t)(ntile * qtotal + qb) * (NT * 4);
        const int total = (qe - qb) * (NT * 4);
        for (int e = tid; e < total; e += 256) {
            int ch = e / (NT * 4), r = e - ch * (NT * 4);
            cpa16(Bres + ch * BSM + (r >> 2) * 80 + (r & 3) * 16, bt + e);
        }
    }
    stage(qb, 0);

    for (int q = qb; q < qe; ++q) {
        int cb = (q - qb) & 1;
        asm volatile("cp.async.wait_group 0;" ::: "memory");
        __syncthreads();
        if (q + 1 < qe) stage(q + 1, cb ^ 1);
        uint32 Ab = sb + cb * BUFSZ;
        uint32 Bb = BRES ? (Bres + (q - qb) * BSM) : (Ab + ABYTES);
#pragma unroll
        for (int g = 0; g < 2; ++g) {
            uint32 bh[NI][2];
#pragma unroll
            for (int ni = 0; ni < NI; ++ni)
                ldsm2(Bb + (brow0 + ni * 8) * 80 + g * 32 + bsegh * 16, bh[ni]);
#pragma unroll
            for (int mi = 0; mi < MI; ++mi) {
                int row = arow0 + mi * 16;
                uint32 ad = Ab + row * 80 + g * 32 + asegh * 16;
                uint32 a[4];
                ldsm4(ad, a);
#pragma unroll
                for (int ni = 0; ni < NI; ++ni) mmaF16(acc[mi][ni], a, bh[ni]);
                ldsm4(ad + APLANE, a);
#pragma unroll
                for (int ni = 0; ni < NI; ++ni) mmaF16(acc[mi][ni], a, bh[ni]);
            }
        }
    }

    const int gID = L >> 2, tg = L & 3;
#pragma unroll
    for (int mi = 0; mi < MI; ++mi)
#pragma unroll
        for (int ni = 0; ni < NI; ++ni) {
            int m = mtile * 128 + warpM + mi * 16 + gID;
            int col = ntile * NT + warpN + ni * 8 + tg * 2;
            float x0 = acc[mi][ni][0], x1 = acc[mi][ni][1];
            float x2 = acc[mi][ni][2], x3 = acc[mi][ni][3];
            if (bias) {
                float2 bb = *(const float2*)(bias + col);
                x0 += bb.x; x1 += bb.y; x2 += bb.x; x3 += bb.y;
            }
            if (dorelu) {
                x0 = fmaxf(x0, 0.f); x1 = fmaxf(x1, 0.f);
                x2 = fmaxf(x2, 0.f); x3 = fmaxf(x3, 0.f);
            }
            if (Cf) {
                *(float2*)(Cf + (size_t)m * ldc + col) = make_float2(x0, x1);
                *(float2*)(Cf + (size_t)(m + 8) * ldc + col) = make_float2(x2, x3);
            } else {
                uint32 lo, hi;
                hi = packsplit(x0, x1, lo);
                *(uint32*)(Ch + (size_t)m * ldc + col) = hi;
                *(uint32*)(Cl + (size_t)m * ldc + col) = lo;
                hi = packsplit(x2, x3, lo);
                *(uint32*)(Ch + (size_t)(m + 8) * ldc + col) = hi;
                *(uint32*)(Cl + (size_t)(m + 8) * ldc + col) = lo;
            }
        }
}

// ---------------- split-K reduce + bias + relu ----------------
__global__ void reduce_kernel(const float* __restrict__ bias, float* __restrict__ outp,
                              int N, int nparts, int stride, int count, int dorelu) {
    int i = blockIdx.x * blockDim.x + threadIdx.x;
    if (i >= count) return;
    float s = 0.f;
    for (int ss = 0; ss < nparts; ++ss) s += g_part[(size_t)ss * stride + i];
    s += bias[i % N];
    outp[i] = dorelu ? fmaxf(s, 0.f) : s;
}

// ---------------- wfeat = g_h @ Ww + bw ----------------
__global__ void __launch_bounds__(256) wfeat_kernel(const float* __restrict__ Ww,
                                                    const float* __restrict__ bw) {
    int t = blockIdx.x * 256 + threadIdx.x;
    int n = t >> 5, oc = t & 31;
    const float* hrow = g_h + (size_t)n * 512;
    float s = bw[oc];
#pragma unroll 8
    for (int k = 0; k < 512; ++k) s += hrow[k] * Ww[k * 32 + oc];
    g_wfeat[t] = s;
}

// ---------------- sequential scan ----------------
__global__ void __launch_bounds__(256) scan_kernel(const float* __restrict__ done,
                                                   const float* __restrict__ state0,
                                                   const int* __restrict__ position,
                                                   float* __restrict__ out_state) {
    const int b = blockIdx.x, cq = blockIdx.y * 2, j = threadIdx.x;
    float st[2];
#pragma unroll
    for (int c = 0; c < 2; ++c) st[c] = state0[b * 8192 + (cq + c) * 256 + j];
    for (int t = 0; t < 32; ++t) {
        int idx = t * 64 + b;
        float m = 1.0f - done[idx];
#pragma unroll
        for (int c = 0; c < 2; ++c) st[c] *= m;
        int p0 = position[idx * 2], p1 = position[idx * 2 + 1];
        if (j == p0 * 16 + p1) {
#pragma unroll
            for (int c = 0; c < 2; ++c) st[c] += g_wfeat[idx * 32 + cq + c];
        }
        size_t rb = (size_t)idx * 8256;
#pragma unroll
        for (int c = 0; c < 2; ++c) {
            __half h = __float2half_rn(st[c]);
            g_hidh[rb + (cq + c) * 256 + j] = __half_as_ushort(h);
            g_hidl[rb + (cq + c) * 256 + j] =
                __half_as_ushort(__float2half_rn(st[c] - __half2float(h)));
        }
    }
#pragma unroll
    for (int c = 0; c < 2; ++c) out_state[b * 8192 + (cq + c) * 256 + j] = st[c];
}

// ---------------- pos_net ----------------
__global__ void __launch_bounds__(64) posnet_kernel(const int* __restrict__ position,
                                                    const float* __restrict__ wp1,
                                                    const float* __restrict__ bp1,
                                                    const float* __restrict__ wp2,
                                                    const float* __restrict__ bp2) {
    __shared__ float hr[64];
    const int n = blockIdx.x, k = threadIdx.x;
    int p0 = position[n * 2], p1 = position[n * 2 + 1];
    hr[k] = fmaxf(wp1[p0 * 64 + k] + wp1[(16 + p1) * 64 + k] + bp1[k], 0.f);
    __syncthreads();
    float s = bp2[k];
#pragma unroll 8
    for (int j = 0; j < 64; ++j) s += hr[j] * wp2[j * 64 + k];
    __half h = __float2half_rn(s);
    g_hidh[(size_t)n * 8256 + 8192 + k] = __half_as_ushort(h);
    g_hidl[(size_t)n * 8256 + 8192 + k] =
        __half_as_ushort(__float2half_rn(s - __half2float(h)));
}

// ---------------- heads ----------------
__global__ void heads_kernel(const float* __restrict__ wpo2, const float* __restrict__ bpo2,
                             const float* __restrict__ wv2, const float* __restrict__ bv2,
                             float* __restrict__ out_logits, float* __restrict__ out_v) {
    int n = blockIdx.x * blockDim.x + threadIdx.x;
    if (n >= 2048) return;
    const float* z = g_z + (size_t)n * 128;
    float lg[5];
#pragma unroll
    for (int a = 0; a < 5; ++a) lg[a] = bpo2[a];
    float vv = bv2[0];
#pragma unroll 4
    for (int j = 0; j < 64; ++j) {
        float zj = z[j];
#pragma unroll
        for (int a = 0; a < 5; ++a) lg[a] += zj * wpo2[j * 5 + a];
        vv += z[64 + j] * wv2[j];
    }
#pragma unroll
    for (int a = 0; a < 5; ++a) out_logits[n * 5 + a] = lg[a];
    out_v[n] = vv;
}

// ---------------- launch ----------------
extern "C" void kernel_launch(void* const* d_in, const int* in_sizes, int n_in,
                              void* d_out, int out_size) {
    bool dict_order = (in_sizes[3] == 4096 && in_sizes[4] == 6144);
    int wb = dict_order ? 4 : 3;
    int posIdx = dict_order ? 3 : 25;

    const float* image  = (const float*)d_in[0];
    const float* done   = (const float*)d_in[1];
    const float* state0 = (const float*)d_in[2];
    const int*   position = (const int*)d_in[posIdx];
    const float* w1  = (const float*)d_in[wb + 0];
    const float* b1  = (const float*)d_in[wb + 1];
    const float* w2  = (const float*)d_in[wb + 2];
    const float* b2  = (const float*)d_in[wb + 3];
    const float* w3  = (const float*)d_in[wb + 4];
    const float* b3  = (const float*)d_in[wb + 5];
    const float* wfc = (const float*)d_in[wb + 6];
    const float* bfc = (const float*)d_in[wb + 7];
    const float* Ww  = (const float*)d_in[wb + 8];
    const float* bw  = (const float*)d_in[wb + 9];
    const float* wp1 = (const float*)d_in[wb + 10];
    const float* bp1 = (const float*)d_in[wb + 11];
    const float* wp2 = (const float*)d_in[wb + 12];
    const float* bp2 = (const float*)d_in[wb + 13];
    const float* wpo1 = (const float*)d_in[wb + 14];
    const float* bpo1 = (const float*)d_in[wb + 15];
    const float* wpo2 = (const float*)d_in[wb + 16];
    const float* bpo2 = (const float*)d_in[wb + 17];
    const float* wv1 = (const float*)d_in[wb + 18];
    const float* bv1 = (const float*)d_in[wb + 19];
    const float* wv2 = (const float*)d_in[wb + 20];
    const float* bv2 = (const float*)d_in[wb + 21];

    float* out = (float*)d_out;
    float* out_logits = out;
    float* out_v      = out + 10240;
    float* out_state  = out + 12288;

    ush *p_imgh, *p_imgl, *p_a1h, *p_a1l, *p_a2h, *p_a2l, *p_a3h, *p_a3l, *p_hidh, *p_hidl;
    float *p_h, *p_part, *p_z, *p_bcat;
    uint4 *p_w1sw, *p_w2sw, *p_w3sw, *p_wfcsw, *p_wposw;
    cudaGetSymbolAddress((void**)&p_imgh, g_imgh);
    cudaGetSymbolAddress((void**)&p_imgl, g_imgl);
    cudaGetSymbolAddress((void**)&p_a1h, g_a1h);
    cudaGetSymbolAddress((void**)&p_a1l, g_a1l);
    cudaGetSymbolAddress((void**)&p_a2h, g_a2h);
    cudaGetSymbolAddress((void**)&p_a2l, g_a2l);
    cudaGetSymbolAddress((void**)&p_a3h, g_a3h);
    cudaGetSymbolAddress((void**)&p_a3l, g_a3l);
    cudaGetSymbolAddress((void**)&p_hidh, g_hidh);
    cudaGetSymbolAddress((void**)&p_hidl, g_hidl);
    cudaGetSymbolAddress((void**)&p_h, g_h);
    cudaGetSymbolAddress((void**)&p_part, g_part);
    cudaGetSymbolAddress((void**)&p_z, g_z);
    cudaGetSymbolAddress((void**)&p_bcat, g_bcat);
    cudaGetSymbolAddress((void**)&p_w1sw, g_w1sw);
    cudaGetSymbolAddress((void**)&p_w2sw, g_w2sw);
    cudaGetSymbolAddress((void**)&p_w3sw, g_w3sw);
    cudaGetSymbolAddress((void**)&p_wfcsw, g_wfcsw);
    cudaGetSymbolAddress((void**)&p_wposw, g_wposw);

    const int SM64 = 2 * (20480 + 64 * 80);        // 51200 (MODE 0)
    const int SM1  = 2 * 20480 + 6 * (32 * 80);    // 56320 (conv1)
    const int SMC2 = 2 * (400 * 80) + 2 * 5120;    // 74240 (convR<2>)
    const int SMC3 = 2 * (2 * 81 * 144) + 2 * 5120; // 56896 (convR<3>)
    const int SMIMG = 21168 * 4;
    cudaFuncSetAttribute(imgprep_kernel, cudaFuncAttributeMaxDynamicSharedMemorySize, SMIMG);
    cudaFuncSetAttribute(gemmP<3,32>, cudaFuncAttributeMaxDynamicSharedMemorySize, SM1);
    cudaFuncSetAttribute(gemmP<0,64>, cudaFuncAttributeMaxDynamicSharedMemorySize, SM64);
    cudaFuncSetAttribute(convR<2>, cudaFuncAttributeMaxDynamicSharedMemorySize, SMC2);
    cudaFuncSetAttribute(convR<3>, cudaFuncAttributeMaxDynamicSharedMemorySize, SMC3);

    prep_kernel<<<392, 512>>>(w1, w2, w3, wpo1, wv1, wfc, bpo1, bv1);
    imgprep_kernel<<<2048, 256, SMIMG>>>(image);
    // conv1: M=819200, N=32, K=192 (6 chunks, channel-planar, B-resident)
    gemmP<3,32><<<dim3(1, 6400, 1), 256, SM1>>>(p_imgh, p_imgl, 0, p_w1sw, 6, 6,
                                                (float*)0, p_a1h, p_a1l, 32, 819200, b1, 1);
    // conv2 image-resident: 1 image/CTA
    convR<2><<<2048, 192, SMC2>>>(p_a1h, p_a1l, p_w2sw, p_a2h, p_a2l, b2);
    // conv3 image-resident: 2 images/CTA
    convR<3><<<1024, 256, SMC3>>>(p_a2h, p_a2l, p_w3sw, p_a3h, p_a3l, b3);
    // FC: M=2048, N=512 (8 ntiles), K=3136 (98 chunks), split-K=2
    gemmP<0,64><<<dim3(8, 16, 2), 256, SM64>>>(p_a3h, p_a3l, 3136, p_wfcsw, 98, 49,
                                               p_part, (ush*)0, (ush*)0, 512, 2048,
                                               (const float*)0, 0);
    reduce_kernel<<<2048, 512>>>(bfc, p_h, 512, 2, 2048 * 512, 2048 * 512, 1);
    wfeat_kernel<<<256, 256>>>(Ww, bw);
    scan_kernel<<<dim3(64, 16, 1), 256>>>(done, state0, position, out_state);
    posnet_kernel<<<2048, 64>>>(position, wp1, bp1, wp2, bp2);
    // policy/value: M=2048, N=128 (2 ntiles), K=8256 (258 chunks), split-K=8
    gemmP<0,64><<<dim3(2, 16, 8), 256, SM64>>>(p_hidh, p_hidl, 8256, p_wposw, 258, 33,
                                               p_part, (ush*)0, (ush*)0, 128, 2048,
                                               (const float*)0, 0);
    reduce_kernel<<<512, 512>>>(p_bcat, p_z, 128, 8, 2048 * 128, 2048 * 128, 1);
    heads_kernel<<<16, 128>>>(wpo2, bpo2, wv2, bv2, out_logits, out_v);
}

// round 16
// speedup vs baseline: 1.1231x; 1.0195x over previous
#include <cuda_runtime.h>
#include <cuda_fp16.h>
#include <cstdint>

typedef unsigned short ush;
typedef unsigned int uint32;

// ---------------- scratch (device globals; zero-initialized, no allocation) ----------------
__device__ ush g_imgh[2048 * 3 * 7056];   // image fp16 hi, planar [n][c][y*84+x]
__device__ ush g_imgl[2048 * 3 * 7056];
__device__ ush g_a1h[2048 * 400 * 32];    // conv1 out planes [n*400+p][32]
__device__ ush g_a1l[2048 * 400 * 32];
__device__ ush g_a2h[2048 * 81 * 64];     // conv2 out planes
__device__ ush g_a2l[2048 * 81 * 64];
__device__ ush g_a3h[2048 * 49 * 64];     // conv3 out planes [n*49+p][64]
__device__ ush g_a3l[2048 * 49 * 64];
__device__ ush g_hidh[2048 * 8256];       // hidden planes [map 8192 | pos 64]
__device__ ush g_hidl[2048 * 8256];
__device__ float g_h[2048 * 512];
__device__ float g_wfeat[2048 * 32];
__device__ float g_part[2 * 2048 * 512];
__device__ float g_z[2048 * 128];
__device__ float g_bcat[128];
// fp16 weight tiles (hi only), packed rows: chunk tile = NT rows x 64 bytes (32 k's).
__device__ uint4 g_w1sw[6 * 128];         // conv1: 6 chunks x 2KB (NT=32)
__device__ uint4 g_w2sw[16 * 256];        // conv2: 16 chunks x 4KB
__device__ uint4 g_w3sw[18 * 256];        // conv3: 18 chunks
__device__ uint4 g_wfcsw[8 * 98 * 256];   // FC: 8 ntiles x 98 chunks
__device__ uint4 g_wposw[2 * 258 * 256];  // policy: 2 ntiles x 258 chunks

// ---------------- helpers ----------------
static __device__ __forceinline__ uint32 s2u(const void* p) {
    uint32 a;
    asm("{ .reg .u64 t; cvta.to.shared.u64 t, %1; cvt.u32.u64 %0, t; }" : "=r"(a) : "l"(p));
    return a;
}
static __device__ __forceinline__ void cpa16(uint32 d, const void* s) {
    asm volatile("cp.async.cg.shared.global [%0], [%1], 16;" :: "r"(d), "l"(s));
}
static __device__ __forceinline__ void cpa8(uint32 d, const void* s) {
    asm volatile("cp.async.ca.shared.global [%0], [%1], 8;" :: "r"(d), "l"(s));
}
static __device__ __forceinline__ void ldsm4(uint32 addr, uint32* r) {
    asm volatile("ldmatrix.sync.aligned.m8n8.x4.shared.b16 {%0,%1,%2,%3}, [%4];"
                 : "=r"(r[0]), "=r"(r[1]), "=r"(r[2]), "=r"(r[3]) : "r"(addr));
}
static __device__ __forceinline__ void ldsm2(uint32 addr, uint32* r) {
    asm volatile("ldmatrix.sync.aligned.m8n8.x2.shared.b16 {%0,%1}, [%2];"
                 : "=r"(r[0]), "=r"(r[1]) : "r"(addr));
}
static __device__ __forceinline__ void mmaF16(float* c, const uint32* a, const uint32* b) {
    asm volatile(
        "mma.sync.aligned.m16n8k16.row.col.f32.f16.f16.f32 "
        "{%0,%1,%2,%3}, {%4,%5,%6,%7}, {%8,%9}, {%0,%1,%2,%3};"
        : "+f"(c[0]), "+f"(c[1]), "+f"(c[2]), "+f"(c[3])
        : "r"(a[0]), "r"(a[1]), "r"(a[2]), "r"(a[3]), "r"(b[0]), "r"(b[1]));
}
static __device__ __forceinline__ uint32 packsplit(float x0, float x1, uint32& lo) {
    __half h0 = __float2half_rn(x0), h1 = __float2half_rn(x1);
    __half l0 = __float2half_rn(x0 - __half2float(h0));
    __half l1 = __float2half_rn(x1 - __half2float(h1));
    lo = (uint32)__half_as_ushort(l0) | ((uint32)__half_as_ushort(l1) << 16);
    return (uint32)__half_as_ushort(h0) | ((uint32)__half_as_ushort(h1) << 16);
}

// ---------------- prep: vectorized weight quantize (8 k's -> one uint4 store) ----------------
static __device__ __forceinline__ void st8(uint4* tiles, int tilebytes, int tile,
                                           int nn, int kk8, const float* v, int stride) {
    ush h[8];
#pragma unroll
    for (int j = 0; j < 8; ++j) h[j] = __half_as_ushort(__float2half_rn(v[j * stride]));
    uint4 pk;
    pk.x = (uint32)h[0] | ((uint32)h[1] << 16);
    pk.y = (uint32)h[2] | ((uint32)h[3] << 16);
    pk.z = (uint32)h[4] | ((uint32)h[5] << 16);
    pk.w = (uint32)h[6] | ((uint32)h[7] << 16);
    *(uint4*)((char*)tiles + (size_t)tile * tilebytes + nn * 64 + kk8 * 16) = pk;
}

__global__ void prep_kernel(const float* __restrict__ w1, const float* __restrict__ w2,
                            const float* __restrict__ w3, const float* __restrict__ wpo1,
                            const float* __restrict__ wv1, const float* __restrict__ wfc,
                            const float* __restrict__ bpo1, const float* __restrict__ bv1) {
    int i = blockIdx.x * blockDim.x + threadIdx.x;
    if (i < 768) {   // conv1: k = c*64+ks contiguous in w1 row
        int oc = i / 24, kv = i - oc * 24, k0 = kv * 8;
        st8(g_w1sw, 2048, k0 >> 5, oc, (k0 & 31) >> 3, w1 + oc * 192 + k0, 1);
    }
    if (i < 4096) {  // conv2: k = ks*32+c; src w2[oc*512 + c*16 + ks]
        int oc = i & 63, kv = i >> 6, k0 = kv * 8;
        int ks = k0 >> 5, c0 = k0 & 31;
        st8(g_w2sw, 4096, ks, oc, c0 >> 3, w2 + oc * 512 + c0 * 16 + ks, 16);
    }
    if (i < 4608) {  // conv3: tile = ks*2+(c>>5); src w3[oc*576 + c*9 + ks]
        int oc = i / 72, kv = i - oc * 72;
        int ks = kv >> 3, c0 = (kv & 7) * 8;
        st8(g_w3sw, 4096, ks * 2 + (c0 >> 5), oc, (c0 & 31) >> 3, w3 + oc * 576 + c0 * 9 + ks, 9);
    }
    if (i < 132096) { // policy/value concat: src stride 64 over k
        int kv = i >> 7, n = i & 127, k0 = kv * 8;
        const float* src = (n < 64) ? (wpo1 + (size_t)k0 * 64 + n)
                                    : (wv1 + (size_t)k0 * 64 + (n - 64));
        st8(g_wposw, 4096, (n >> 6) * 258 + (k0 >> 5), n & 63, (k0 & 31) >> 3, src, 64);
    }
    if (i < 200704) { // FC: k=p*64+c; src wfc[(c*49+p)*512 + n]
        int kv = i >> 9, n = i & 511, k0 = kv * 8;
        int p = k0 >> 6, c0 = k0 & 63;
        st8(g_wfcsw, 4096, (n >> 6) * 98 + p * 2 + (c0 >> 5), n & 63, (c0 & 31) >> 3,
            wfc + ((size_t)c0 * 49 + p) * 512 + n, 49 * 512);
    }
    if (i < 128) g_bcat[i] = (i < 64) ? bpo1[i] : bv1[i - 64];
}

// ---------------- image -> planar fp16 hi/lo, smem-coalesced (fused /255) ----------------
__global__ void __launch_bounds__(256) imgprep_kernel(const float* __restrict__ img) {
    extern __shared__ float spix[];
    const int n = blockIdx.x, tid = threadIdx.x;
    const float4* src = (const float4*)(img + (size_t)n * 21168);
    for (int i = tid; i < 5292; i += 256) ((float4*)spix)[i] = src[i];
    __syncthreads();
#pragma unroll
    for (int c = 0; c < 3; ++c) {
        size_t ob = ((size_t)n * 3 + c) * 7056;
        for (int pp = tid; pp < 3528; pp += 256) {
            float v0 = spix[(pp * 2) * 3 + c] * (1.f / 255.f);
            float v1 = spix[(pp * 2 + 1) * 3 + c] * (1.f / 255.f);
            uint32 lo, hi = packsplit(v0, v1, lo);
            *(uint32*)(g_imgh + ob + pp * 2) = hi;
            *(uint32*)(g_imgl + ob + pp * 2) = lo;
        }
    }
}

// ================= image-resident conv GEMM (conv2 / conv3) =================
// conv2: resident image stored as 4 parity sub-grids (y&1,x&1) of 10x10 px,
// 80B rows -> ldmatrix lane stride 80B = 5 banks (odd) = conflict-free.
// conv3: flat 81 px at 144B stride (9 banks, odd) = already conflict-free.
template<int CONV>
__global__ void __launch_bounds__(CONV == 2 ? 192 : 256, 2) convR(
    const ush* __restrict__ Ah, const ush* __restrict__ Al,
    const uint4* __restrict__ Bt,
    ush* __restrict__ Ch, ush* __restrict__ Cl,
    const float* __restrict__ bias)
{
    constexpr int PSTR  = (CONV == 2) ? 80 : 144;
    constexpr int NPIX  = (CONV == 2) ? 400 : 81;
    constexpr int NIMG  = (CONV == 2) ? 1 : 2;
    constexpr int ROWB  = (CONV == 2) ? 64 : 128;
    constexpr int SUBG  = 100 * 80;                   // conv2 sub-grid bytes (10x10)
    constexpr int IPLANE = NPIX * PSTR;               // 32000 / 11664
    constexpr int AHALF  = IPLANE * NIMG;
    constexpr int ATOT   = 2 * AHALF;
    constexpr int QTOT  = (CONV == 2) ? 16 : 18;
    constexpr int THR   = (CONV == 2) ? 192 : 256;
    constexpr int BSM   = 64 * 80;
    extern __shared__ __align__(16) char smem[];
    const uint32 sb = s2u(smem);
    const uint32 Bb0 = sb + ATOT;
    const int tid = threadIdx.x, blk = blockIdx.x;

    // ---- prologue: resident A (hi+lo) + B chunk 0 ----
    for (int r = tid; r < NPIX * NIMG; r += THR) {
        int img = r / NPIX, p = r - img * NPIX;
        uint32 d;
        if (CONV == 2) {
            int y = p / 20, x = p - (p / 20) * 20;
            d = sb + ((y & 1) * 2 + (x & 1)) * SUBG + ((y >> 1) * 10 + (x >> 1)) * 80;
        } else {
            d = sb + img * IPLANE + p * PSTR;
        }
        const char* gh = (const char*)(Ah + ((size_t)(blk * NIMG + img) * NPIX + p) * (ROWB / 2));
        const char* gl = (const char*)(Al + ((size_t)(blk * NIMG + img) * NPIX + p) * (ROWB / 2));
#pragma unroll
        for (int s = 0; s < ROWB / 16; ++s) {
            cpa16(d + s * 16, gh + s * 16);
            cpa16(d + AHALF + s * 16, gl + s * 16);
        }
    }
    for (int e = tid; e < 256; e += THR)
        cpa16(Bb0 + (e >> 2) * 80 + (e & 3) * 16, Bt + e);
    asm volatile("cp.async.commit_group;" ::: "memory");

    // ---- lane geometry ----
    const int wid = tid >> 5, L = tid & 31;
    const int warpM = (CONV == 2) ? (wid % 3) * 32 : (wid & 3) * 32;
    const int warpN = (CONV == 2) ? (wid / 3) * 32 : (wid >> 2) * 32;
    const int t4 = L >> 3;
    const int mA0 = warpM + (t4 & 1) * 8 + (L & 7);
    const int kbyte = (t4 >> 1) * 16;
    uint32 aconst[2];
#pragma unroll
    for (int mi = 0; mi < 2; ++mi) {
        int m = mA0 + mi * 16;
        if (CONV == 2) {
            int row = (m < 81) ? m : 0;
            int oy = row / 9, ox = row - oy * 9;
            aconst[mi] = sb + (oy * 10 + ox) * 80 + kbyte;   // position within sub-grid
        } else {
            int img = m >> 6, row = ((m & 63) < 49) ? (m & 63) : 0;
            int oy = row / 7, ox = row - oy * 7;
            aconst[mi] = sb + img * IPLANE + (oy * 9 + ox) * PSTR + kbyte;
        }
    }
    const int brow0 = warpN + (L & 7);
    const int bsegh = (L >> 3) & 1;

    float acc[2][4][4];
#pragma unroll
    for (int mi = 0; mi < 2; ++mi)
#pragma unroll
        for (int ni = 0; ni < 4; ++ni)
#pragma unroll
            for (int r = 0; r < 4; ++r) acc[mi][ni][r] = 0.f;

    for (int q = 0; q < QTOT; ++q) {
        asm volatile("cp.async.wait_group 0;" ::: "memory");
        __syncthreads();
        if (q + 1 < QTOT) {
            const uint4* bt = Bt + (size_t)(q + 1) * 256;
            uint32 Bd = Bb0 + ((q + 1) & 1) * BSM;
            for (int e = tid; e < 256; e += THR)
                cpa16(Bd + (e >> 2) * 80 + (e & 3) * 16, bt + e);
            asm volatile("cp.async.commit_group;" ::: "memory");
        }
        uint32 coff;
        if (CONV == 2) {
            int ky = q >> 2, kx = q & 3;
            coff = ((ky & 1) * 2 + (kx & 1)) * SUBG + ((ky >> 1) * 10 + (kx >> 1)) * 80;
        } else {
            int ks = q >> 1; int ky = ks / 3, kx = ks - ky * 3;
            coff = (ky * 9 + kx) * PSTR + (q & 1) * 64;
        }
        uint32 Bb = Bb0 + (q & 1) * BSM;
#pragma unroll
        for (int g = 0; g < 2; ++g) {
            uint32 bh[4][2];
#pragma unroll
            for (int ni = 0; ni < 4; ++ni)
                ldsm2(Bb + (brow0 + ni * 8) * 80 + g * 32 + bsegh * 16, bh[ni]);
#pragma unroll
            for (int mi = 0; mi < 2; ++mi) {
                uint32 ad = aconst[mi] + coff + g * 32;
                uint32 a[4];
                ldsm4(ad, a);                 // hi plane
#pragma unroll
                for (int ni = 0; ni < 4; ++ni) mmaF16(acc[mi][ni], a, bh[ni]);
                ldsm4(ad + AHALF, a);         // lo plane
#pragma unroll
                for (int ni = 0; ni < 4; ++ni) mmaF16(acc[mi][ni], a, bh[ni]);
            }
        }
    }

    // ---- epilogue ----
    const int gID = L >> 2, tg = L & 3;
#pragma unroll
    for (int mi = 0; mi < 2; ++mi)
#pragma unroll
        for (int ni = 0; ni < 4; ++ni) {
            int col = warpN + ni * 8 + tg * 2;
#pragma unroll
            for (int half = 0; half < 2; ++half) {
                int m = warpM + mi * 16 + gID + half * 8;
                float x0 = acc[mi][ni][half * 2], x1 = acc[mi][ni][half * 2 + 1];
                int img, row, valid;
                if (CONV == 2) { img = 0; row = m; valid = (m < 81); }
                else { img = m >> 6; row = m & 63; valid = (row < 49); }
                if (!valid) continue;
                float2 bb = *(const float2*)(bias + col);
                x0 = fmaxf(x0 + bb.x, 0.f);
                x1 = fmaxf(x1 + bb.y, 0.f);
                uint32 lo, hi = packsplit(x0, x1, lo);
                size_t o = ((size_t)(blk * NIMG + img) * ((CONV == 2) ? 81 : 49) + row) * 64 + col;
                *(uint32*)(Ch + o) = hi;
                *(uint32*)(Cl + o) = lo;
            }
        }
}

// ---------------- depth-2 pipelined mma.sync GEMM (MODE 0 direct, MODE 3 conv1) ----------------
template<int MODE, int NT>
__global__ void __launch_bounds__(256, 3) gemmP(
    const ush* __restrict__ Ah, const ush* __restrict__ Al, int lda,
    const uint4* __restrict__ Bt, int qtotal, int qsplit,
    float* __restrict__ Cf, ush* __restrict__ Ch, ush* __restrict__ Cl,
    int ldc, int Mtotal, const float* __restrict__ bias, int dorelu)
{
    constexpr bool BRES = (MODE == 3);
    constexpr int MI = 2;
    constexpr int NI = NT / 16;
    constexpr int APLANE = 128 * 80;
    constexpr int ABYTES = 2 * APLANE;
    constexpr int BSM = NT * 80;
    constexpr int BUFSZ = ABYTES + (BRES ? 0 : BSM);
    extern __shared__ __align__(16) char smem[];
    const uint32 sb = s2u(smem);
    const uint32 Bres = sb + 2 * BUFSZ;
    const int tid = threadIdx.x;
    const int mtile = blockIdx.y, ntile = blockIdx.x, z = blockIdx.z;
    if (Cf) Cf += (size_t)z * Mtotal * ldc;

    const int arow = tid & 127, ahalf = tid >> 7;
    const int gm = mtile * 128 + arow;
    size_t abase = 0; int oy = 0, ox = 0;
    if (MODE == 0) abase = (size_t)gm * lda;
    else { int n = gm / 400, p = gm - n * 400; oy = p / 20; ox = p - oy * 20; abase = (size_t)n * 21168; }

    const int qb = z * qsplit;
    const int qe = min(qtotal, qb + qsplit);

    auto stage = [&](int q, int buf) {
        uint32 Ab = sb + buf * BUFSZ;
        uint32 rowb = Ab + arow * 80;
        if (MODE == 3) {
            size_t base = abase + (size_t)(q >> 1) * 7056
                        + (size_t)(oy * 4 + (q & 1) * 4 + ahalf * 2) * 84 + ox * 4;
#pragma unroll
            for (int j = 0; j < 2; ++j) {
                const char* gh = (const char*)(Ah + base + j * 84);
                const char* gl = (const char*)(Al + base + j * 84);
                uint32 d = rowb + (ahalf * 2 + j) * 16;
                cpa8(d, gh); cpa8(d + 8, gh + 8);
                cpa8(d + APLANE, gl); cpa8(d + APLANE + 8, gl + 8);
            }
        } else {
            size_t off = abase + (size_t)q * 32 + ahalf * 16;
            const char* gh = (const char*)(Ah + off);
            const char* gl = (const char*)(Al + off);
            uint32 d = rowb + ahalf * 32;
            cpa16(d, gh); cpa16(d + 16, gh + 16);
            cpa16(d + APLANE, gl); cpa16(d + APLANE + 16, gl + 16);
        }
        if (!BRES) {
            uint32 Bb = Ab + ABYTES;
            const uint4* bt = Bt + (size_t)(ntile * qtotal + q) * (NT * 4);
            for (int e = tid; e < NT * 4; e += 256)
                cpa16(Bb + (e >> 2) * 80 + (e & 3) * 16, bt + e);
        }
        asm volatile("cp.async.commit_group;" ::: "memory");
    };

    const int wid = tid >> 5, L = tid & 31;
    const int warpM = (wid & 3) * 32;
    const int warpN = (wid >> 2) * (NI * 8);
    const int arow0 = warpM + (L & 7) + ((L >> 3) & 1) * 8;
    const int asegh = (L >> 4) & 1;
    const int brow0 = warpN + (L & 7);
    const int bsegh = (L >> 3) & 1;

    float acc[MI][NI][4];
#pragma unroll
    for (int mi = 0; mi < MI; ++mi)
#pragma unroll
        for (int ni = 0; ni < NI; ++ni)
#pragma unroll
            for (int r = 0; r < 4; ++r) acc[mi][ni][r] = 0.f;

    if (BRES) {
        const uint4* bt = Bt + (size_t)(ntile * qtotal + qb) * (NT * 4);
        const int total = (qe - qb) * (NT * 4);
        for (int e = tid; e < total; e += 256) {
            int ch = e / (NT * 4), r = e - ch * (NT * 4);
            cpa16(Bres + ch * BSM + (r >> 2) * 80 + (r & 3) * 16, bt + e);
        }
    }
    stage(qb, 0);

    for (int q = qb; q < qe; ++q) {
        int cb = (q - qb) & 1;
        asm volatile("cp.async.wait_group 0;" ::: "memory");
        __syncthreads();
        if (q + 1 < qe) stage(q + 1, cb ^ 1);
        uint32 Ab = sb + cb * BUFSZ;
        uint32 Bb = BRES ? (Bres + (q - qb) * BSM) : (Ab + ABYTES);
#pragma unroll
        for (int g = 0; g < 2; ++g) {
            uint32 bh[NI][2];
#pragma unroll
            for (int ni = 0; ni < NI; ++ni)
                ldsm2(Bb + (brow0 + ni * 8) * 80 + g * 32 + bsegh * 16, bh[ni]);
#pragma unroll
            for (int mi = 0; mi < MI; ++mi) {
                int row = arow0 + mi * 16;
                uint32 ad = Ab + row * 80 + g * 32 + asegh * 16;
                uint32 a[4];
                ldsm4(ad, a);
#pragma unroll
                for (int ni = 0; ni < NI; ++ni) mmaF16(acc[mi][ni], a, bh[ni]);
                ldsm4(ad + APLANE, a);
#pragma unroll
                for (int ni = 0; ni < NI; ++ni) mmaF16(acc[mi][ni], a, bh[ni]);
            }
        }
    }

    const int gID = L >> 2, tg = L & 3;
#pragma unroll
    for (int mi = 0; mi < MI; ++mi)
#pragma unroll
        for (int ni = 0; ni < NI; ++ni) {
            int m = mtile * 128 + warpM + mi * 16 + gID;
            int col = ntile * NT + warpN + ni * 8 + tg * 2;
            float x0 = acc[mi][ni][0], x1 = acc[mi][ni][1];
            float x2 = acc[mi][ni][2], x3 = acc[mi][ni][3];
            if (bias) {
                float2 bb = *(const float2*)(bias + col);
                x0 += bb.x; x1 += bb.y; x2 += bb.x; x3 += bb.y;
            }
            if (dorelu) {
                x0 = fmaxf(x0, 0.f); x1 = fmaxf(x1, 0.f);
                x2 = fmaxf(x2, 0.f); x3 = fmaxf(x3, 0.f);
            }
            if (Cf) {
                *(float2*)(Cf + (size_t)m * ldc + col) = make_float2(x0, x1);
                *(float2*)(Cf + (size_t)(m + 8) * ldc + col) = make_float2(x2, x3);
            } else {
                uint32 lo, hi;
                hi = packsplit(x0, x1, lo);
                *(uint32*)(Ch + (size_t)m * ldc + col) = hi;
                *(uint32*)(Cl + (size_t)m * ldc + col) = lo;
                hi = packsplit(x2, x3, lo);
                *(uint32*)(Ch + (size_t)(m + 8) * ldc + col) = hi;
                *(uint32*)(Cl + (size_t)(m + 8) * ldc + col) = lo;
            }
        }
}

// ---------------- split-K reduce + bias + relu ----------------
__global__ void reduce_kernel(const float* __restrict__ bias, float* __restrict__ outp,
                              int N, int nparts, int stride, int count, int dorelu) {
    int i = blockIdx.x * blockDim.x + threadIdx.x;
    if (i >= count) return;
    float s = 0.f;
    for (int ss = 0; ss < nparts; ++ss) s += g_part[(size_t)ss * stride + i];
    s += bias[i % N];
    outp[i] = dorelu ? fmaxf(s, 0.f) : s;
}

// ---------------- wfeat = g_h @ Ww + bw ----------------
__global__ void __launch_bounds__(256) wfeat_kernel(const float* __restrict__ Ww,
                                                    const float* __restrict__ bw) {
    int t = blockIdx.x * 256 + threadIdx.x;
    int n = t >> 5, oc = t & 31;
    const float* hrow = g_h + (size_t)n * 512;
    float s = bw[oc];
#pragma unroll 8
    for (int k = 0; k < 512; ++k) s += hrow[k] * Ww[k * 32 + oc];
    g_wfeat[t] = s;
}

// ---------------- sequential scan ----------------
__global__ void __launch_bounds__(256) scan_kernel(const float* __restrict__ done,
                                                   const float* __restrict__ state0,
                                                   const int* __restrict__ position,
                                                   float* __restrict__ out_state) {
    const int b = blockIdx.x, cq = blockIdx.y * 2, j = threadIdx.x;
    float st[2];
#pragma unroll
    for (int c = 0; c < 2; ++c) st[c] = state0[b * 8192 + (cq + c) * 256 + j];
    for (int t = 0; t < 32; ++t) {
        int idx = t * 64 + b;
        float m = 1.0f - done[idx];
#pragma unroll
        for (int c = 0; c < 2; ++c) st[c] *= m;
        int p0 = position[idx * 2], p1 = position[idx * 2 + 1];
        if (j == p0 * 16 + p1) {
#pragma unroll
            for (int c = 0; c < 2; ++c) st[c] += g_wfeat[idx * 32 + cq + c];
        }
        size_t rb = (size_t)idx * 8256;
#pragma unroll
        for (int c = 0; c < 2; ++c) {
            __half h = __float2half_rn(st[c]);
            g_hidh[rb + (cq + c) * 256 + j] = __half_as_ushort(h);
            g_hidl[rb + (cq + c) * 256 + j] =
                __half_as_ushort(__float2half_rn(st[c] - __half2float(h)));
        }
    }
#pragma unroll
    for (int c = 0; c < 2; ++c) out_state[b * 8192 + (cq + c) * 256 + j] = st[c];
}

// ---------------- pos_net ----------------
__global__ void __launch_bounds__(64) posnet_kernel(const int* __restrict__ position,
                                                    const float* __restrict__ wp1,
                                                    const float* __restrict__ bp1,
                                                    const float* __restrict__ wp2,
                                                    const float* __restrict__ bp2) {
    __shared__ float hr[64];
    const int n = blockIdx.x, k = threadIdx.x;
    int p0 = position[n * 2], p1 = position[n * 2 + 1];
    hr[k] = fmaxf(wp1[p0 * 64 + k] + wp1[(16 + p1) * 64 + k] + bp1[k], 0.f);
    __syncthreads();
    float s = bp2[k];
#pragma unroll 8
    for (int j = 0; j < 64; ++j) s += hr[j] * wp2[j * 64 + k];
    __half h = __float2half_rn(s);
    g_hidh[(size_t)n * 8256 + 8192 + k] = __half_as_ushort(h);
    g_hidl[(size_t)n * 8256 + 8192 + k] =
        __half_as_ushort(__float2half_rn(s - __half2float(h)));
}

// ---------------- heads ----------------
__global__ void heads_kernel(const float* __restrict__ wpo2, const float* __restrict__ bpo2,
                             const float* __restrict__ wv2, const float* __restrict__ bv2,
                             float* __restrict__ out_logits, float* __restrict__ out_v) {
    int n = blockIdx.x * blockDim.x + threadIdx.x;
    if (n >= 2048) return;
    const float* z = g_z + (size_t)n * 128;
    float lg[5];
#pragma unroll
    for (int a = 0; a < 5; ++a) lg[a] = bpo2[a];
    float vv = bv2[0];
#pragma unroll 4
    for (int j = 0; j < 64; ++j) {
        float zj = z[j];
#pragma unroll
        for (int a = 0; a < 5; ++a) lg[a] += zj * wpo2[j * 5 + a];
        vv += z[64 + j] * wv2[j];
    }
#pragma unroll
    for (int a = 0; a < 5; ++a) out_logits[n * 5 + a] = lg[a];
    out_v[n] = vv;
}

// ---------------- launch ----------------
extern "C" void kernel_launch(void* const* d_in, const int* in_sizes, int n_in,
                              void* d_out, int out_size) {
    bool dict_order = (in_sizes[3] == 4096 && in_sizes[4] == 6144);
    int wb = dict_order ? 4 : 3;
    int posIdx = dict_order ? 3 : 25;

    const float* image  = (const float*)d_in[0];
    const float* done   = (const float*)d_in[1];
    const float* state0 = (const float*)d_in[2];
    const int*   position = (const int*)d_in[posIdx];
    const float* w1  = (const float*)d_in[wb + 0];
    const float* b1  = (const float*)d_in[wb + 1];
    const float* w2  = (const float*)d_in[wb + 2];
    const float* b2  = (const float*)d_in[wb + 3];
    const float* w3  = (const float*)d_in[wb + 4];
    const float* b3  = (const float*)d_in[wb + 5];
    const float* wfc = (const float*)d_in[wb + 6];
    const float* bfc = (const float*)d_in[wb + 7];
    const float* Ww  = (const float*)d_in[wb + 8];
    const float* bw  = (const float*)d_in[wb + 9];
    const float* wp1 = (const float*)d_in[wb + 10];
    const float* bp1 = (const float*)d_in[wb + 11];
    const float* wp2 = (const float*)d_in[wb + 12];
    const float* bp2 = (const float*)d_in[wb + 13];
    const float* wpo1 = (const float*)d_in[wb + 14];
    const float* bpo1 = (const float*)d_in[wb + 15];
    const float* wpo2 = (const float*)d_in[wb + 16];
    const float* bpo2 = (const float*)d_in[wb + 17];
    const float* wv1 = (const float*)d_in[wb + 18];
    const float* bv1 = (const float*)d_in[wb + 19];
    const float* wv2 = (const float*)d_in[wb + 20];
    const float* bv2 = (const float*)d_in[wb + 21];

    float* out = (float*)d_out;
    float* out_logits = out;
    float* out_v      = out + 10240;
    float* out_state  = out + 12288;

    ush *p_imgh, *p_imgl, *p_a1h, *p_a1l, *p_a2h, *p_a2l, *p_a3h, *p_a3l, *p_hidh, *p_hidl;
    float *p_h, *p_part, *p_z, *p_bcat;
    uint4 *p_w1sw, *p_w2sw, *p_w3sw, *p_wfcsw, *p_wposw;
    cudaGetSymbolAddress((void**)&p_imgh, g_imgh);
    cudaGetSymbolAddress((void**)&p_imgl, g_imgl);
    cudaGetSymbolAddress((void**)&p_a1h, g_a1h);
    cudaGetSymbolAddress((void**)&p_a1l, g_a1l);
    cudaGetSymbolAddress((void**)&p_a2h, g_a2h);
    cudaGetSymbolAddress((void**)&p_a2l, g_a2l);
    cudaGetSymbolAddress((void**)&p_a3h, g_a3h);
    cudaGetSymbolAddress((void**)&p_a3l, g_a3l);
    cudaGetSymbolAddress((void**)&p_hidh, g_hidh);
    cudaGetSymbolAddress((void**)&p_hidl, g_hidl);
    cudaGetSymbolAddress((void**)&p_h, g_h);
    cudaGetSymbolAddress((void**)&p_part, g_part);
    cudaGetSymbolAddress((void**)&p_z, g_z);
    cudaGetSymbolAddress((void**)&p_bcat, g_bcat);
    cudaGetSymbolAddress((void**)&p_w1sw, g_w1sw);
    cudaGetSymbolAddress((void**)&p_w2sw, g_w2sw);
    cudaGetSymbolAddress((void**)&p_w3sw, g_w3sw);
    cudaGetSymbolAddress((void**)&p_wfcsw, g_wfcsw);
    cudaGetSymbolAddress((void**)&p_wposw, g_wposw);

    const int SM64 = 2 * (20480 + 64 * 80);        // 51200 (MODE 0)
    const int SM1  = 2 * 20480 + 6 * (32 * 80);    // 56320 (conv1)
    const int SMC2 = 2 * (400 * 80) + 2 * 5120;    // 74240 (convR<2>)
    const int SMC3 = 2 * (2 * 81 * 144) + 2 * 5120; // 56896 (convR<3>)
    const int SMIMG = 21168 * 4;
    cudaFuncSetAttribute(imgprep_kernel, cudaFuncAttributeMaxDynamicSharedMemorySize, SMIMG);
    cudaFuncSetAttribute(gemmP<3,32>, cudaFuncAttributeMaxDynamicSharedMemorySize, SM1);
    cudaFuncSetAttribute(gemmP<0,64>, cudaFuncAttributeMaxDynamicSharedMemorySize, SM64);
    cudaFuncSetAttribute(convR<2>, cudaFuncAttributeMaxDynamicSharedMemorySize, SMC2);
    cudaFuncSetAttribute(convR<3>, cudaFuncAttributeMaxDynamicSharedMemorySize, SMC3);

    prep_kernel<<<392, 512>>>(w1, w2, w3, wpo1, wv1, wfc, bpo1, bv1);
    imgprep_kernel<<<2048, 256, SMIMG>>>(image);
    // conv1: M=819200, N=32, K=192 (6 chunks, channel-planar, B-resident)
    gemmP<3,32><<<dim3(1, 6400, 1), 256, SM1>>>(p_imgh, p_imgl, 0, p_w1sw, 6, 6,
                                                (float*)0, p_a1h, p_a1l, 32, 819200, b1, 1);
    // conv2 image-resident (parity sub-grids): 1 image/CTA
    convR<2><<<2048, 192, SMC2>>>(p_a1h, p_a1l, p_w2sw, p_a2h, p_a2l, b2);
    // conv3 image-resident: 2 images/CTA
    convR<3><<<1024, 256, SMC3>>>(p_a2h, p_a2l, p_w3sw, p_a3h, p_a3l, b3);
    // FC: M=2048, N=512 (8 ntiles), K=3136 (98 chunks), split-K=2
    gemmP<0,64><<<dim3(8, 16, 2), 256, SM64>>>(p_a3h, p_a3l, 3136, p_wfcsw, 98, 49,
                                               p_part, (ush*)0, (ush*)0, 512, 2048,
                                               (const float*)0, 0);
    reduce_kernel<<<2048, 512>>>(bfc, p_h, 512, 2, 2048 * 512, 2048 * 512, 1);
    wfeat_kernel<<<256, 256>>>(Ww, bw);
    scan_kernel<<<dim3(64, 16, 1), 256>>>(done, state0, position, out_state);
    posnet_kernel<<<2048, 64>>>(position, wp1, bp1, wp2, bp2);
    // policy/value: M=2048, N=128 (2 ntiles), K=8256 (258 chunks), split-K=8
    gemmP<0,64><<<dim3(2, 16, 8), 256, SM64>>>(p_hidh, p_hidl, 8256, p_wposw, 258, 33,
                                               p_part, (ush*)0, (ush*)0, 128, 2048,
                                               (const float*)0, 0);
    reduce_kernel<<<512, 512>>>(p_bcat, p_z, 128, 8, 2048 * 128, 2048 * 128, 1);
    heads_kernel<<<16, 128>>>(wpo2, bpo2, wv2, bv2, out_logits, out_v);
}